// round 8
// baseline (speedup 1.0000x reference)
#include <cuda_runtime.h>
#include <cuda_bf16.h>
#include <cstdint>

#define EPSV 1e-5f
#define B_   4
#define C_   96
#define HW   4096
#define OCT  166     // 18 + 50 + 98 offset channels
#define OCP  192     // padded
#define KOF  864     // 9*96 offset-conv K
#define KP   320     // g_xc row stride (288 used)
#define O_   192

// ---------------- scratch (static device globals) -----------------------------
__device__ float g_off[B_ * OCT * HW];          // offset conv output  [b][oc][p]
__device__ float g_xc [B_ * HW * KP];           // deform output, PIXEL-major [b*HW+p][KP]
__device__ float g_bo [OCP];                    // packed offset bias
__device__ __nv_bfloat16 g_xth[B_ * HW * 96];   // x transposed hi [b*HW+p][c]
__device__ __nv_bfloat16 g_xtl[B_ * HW * 96];   // x transposed lo
__device__ __nv_bfloat16 g_wofh[OCP * KOF];     // offset weights hi [oc][tap*96+c]
__device__ __nv_bfloat16 g_wofl[OCP * KOF];     // offset weights lo
__device__ __nv_bfloat16 g_pwh[O_ * KP];        // pointwise weights hi [o][KP]
__device__ __nv_bfloat16 g_pwl[O_ * KP];        // pointwise weights lo [o][KP]

__device__ __forceinline__ uint32_t smem_u32(const void* p) {
    uint32_t a;
    asm("{ .reg .u64 t; cvta.to.shared.u64 t, %1; cvt.u32.u64 %0, t; }" : "=r"(a) : "l"(p));
    return a;
}
#define LDSM4(r, addr) \
    asm volatile("ldmatrix.sync.aligned.m8n8.x4.shared.b16 {%0,%1,%2,%3}, [%4];" \
        : "=r"((r)[0]), "=r"((r)[1]), "=r"((r)[2]), "=r"((r)[3]) : "r"(addr))
#define LDSM2(r, addr) \
    asm volatile("ldmatrix.sync.aligned.m8n8.x2.shared.b16 {%0,%1}, [%2];" \
        : "=r"((r)[0]), "=r"((r)[1]) : "r"(addr))
#define MMA_BF16(d, a, b) \
    asm volatile("mma.sync.aligned.m16n8k16.row.col.f32.bf16.bf16.f32 " \
        "{%0,%1,%2,%3}, {%4,%5,%6,%7}, {%8,%9}, {%0,%1,%2,%3};" \
        : "+f"((d)[0]), "+f"((d)[1]), "+f"((d)[2]), "+f"((d)[3]) \
        : "r"((a)[0]), "r"((a)[1]), "r"((a)[2]), "r"((a)[3]), "r"((b)[0]), "r"((b)[1]))

// shared GEMM smem geometry (A 128 x 32k, B 192 x 32k, hi/lo)
#define ST    56
#define A_HI  0
#define A_LO  14336
#define B_HI  28672
#define B_LO  50176
#define GEMM_SMEM 71680

// ---------------- prep: pack + bf16-split weights -----------------------------
__global__ void prep_kernel(const float* __restrict__ w3, const float* __restrict__ b3,
                            const float* __restrict__ w5, const float* __restrict__ b5,
                            const float* __restrict__ w7, const float* __restrict__ b7,
                            const float* __restrict__ wpw) {
    int i0 = blockIdx.x * blockDim.x + threadIdx.x;
    int stride = gridDim.x * blockDim.x;
    for (int idx = i0; idx < OCP * KOF; idx += stride) {
        int oc = idx / KOF, k = idx % KOF;
        int r = k / 96, c = k % 96;
        float v = 0.f;
        if (oc < 18)        v = w3[(oc * C_ + c) * 9 + r];
        else if (oc < 68)   v = w5[((oc - 18) * C_ + c) * 9 + r];
        else if (oc < OCT)  v = w7[((oc - 68) * C_ + c) * 9 + r];
        __nv_bfloat16 h = __float2bfloat16(v);
        g_wofh[idx] = h;
        g_wofl[idx] = __float2bfloat16(v - __bfloat162float(h));
    }
    for (int idx = i0; idx < OCP; idx += stride) {
        float v = 0.f;
        if (idx < 18)       v = b3[idx];
        else if (idx < 68)  v = b5[idx - 18];
        else if (idx < OCT) v = b7[idx - 68];
        g_bo[idx] = v;
    }
    for (int idx = i0; idx < O_ * KP; idx += stride) {
        int n = idx / KP, k = idx % KP;
        float w = (k < 288) ? wpw[n * 288 + k] : 0.f;
        __nv_bfloat16 h = __float2bfloat16(w);
        g_pwh[idx] = h;
        g_pwl[idx] = __float2bfloat16(w - __bfloat162float(h));
    }
}

// ---------------- xpose: x [b][c][p] fp32 -> pixel-major bf16 hi/lo ------------
__global__ __launch_bounds__(256) void xpose_kernel(const float* __restrict__ x) {
    int p = blockIdx.x * 256 + threadIdx.x;          // 0..16383 (b*HW+pp)
    int b = p >> 12, pp = p & 4095;
    const float* src = x + (size_t)b * C_ * HW + pp;
    __nv_bfloat16* dh = g_xth + (size_t)p * 96;
    __nv_bfloat16* dl = g_xtl + (size_t)p * 96;
#pragma unroll 8
    for (int c = 0; c < 96; ++c) {
        float v = src[(size_t)c * HW];
        __nv_bfloat16 h = __float2bfloat16(v);
        dh[c] = h;
        dl[c] = __float2bfloat16(v - __bfloat162float(h));
    }
}

// ---------------- K1: offset conv as HMMA implicit GEMM ------------------------
// grid (32 pixel-tiles of 128 px = 2 rows, 1, 4 batch), 256 threads = 8 warps.
// M=128 px, N=192 oc, K=864 (tap-major) in 27 chunks of 32; 3-pass bf16 split.
__global__ __launch_bounds__(256) void offconv_mma_kernel() {
    extern __shared__ char dsm[];
    uint32_t sbase = smem_u32(dsm);
    int tid = threadIdx.x, w = tid >> 5, lane = tid & 31;
    int m0 = (w & 3) * 32, n0 = (w >> 2) * 96;
    int b = blockIdx.z;
    int r0 = blockIdx.x * 2;
    int p0 = blockIdx.x * 128;

    float acc[2][12][4];
#pragma unroll
    for (int i = 0; i < 2; i++)
#pragma unroll
        for (int j = 0; j < 12; j++)
#pragma unroll
            for (int q = 0; q < 4; q++) acc[i][j][q] = 0.f;

    for (int kc = 0; kc < 27; ++kc) {
        int tap = kc / 3, cc = kc - tap * 3;
        int ky = tap / 3 - 1, kx = tap % 3 - 1;
        __syncthreads();
        // stage A: 128 shifted pixels x 32 ch, hi/lo (zeros at border)
        for (int i = tid; i < 512; i += 256) {
            int px = i >> 2, quad = i & 3;
            int row = (px >> 6) + r0 + ky;
            int col = (px & 63) + kx;
            uint32_t off = (uint32_t)((px * ST + quad * 8) * 2);
            if ((unsigned)row < 64u && (unsigned)col < 64u) {
                size_t bp = ((size_t)b * HW + row * 64 + col) * 96 + cc * 32 + quad * 8;
                *(uint4*)(dsm + A_HI + off) = *(const uint4*)(g_xth + bp);
                *(uint4*)(dsm + A_LO + off) = *(const uint4*)(g_xtl + bp);
            } else {
                uint4 z = {0u, 0u, 0u, 0u};
                *(uint4*)(dsm + A_HI + off) = z;
                *(uint4*)(dsm + A_LO + off) = z;
            }
        }
        // stage B: 192 oc x 32 k hi/lo
        for (int i = tid; i < 768; i += 256) {
            int n = i >> 2, quad = i & 3;
            size_t wo = (size_t)n * KOF + kc * 32 + quad * 8;
            uint32_t off = (uint32_t)((n * ST + quad * 8) * 2);
            *(uint4*)(dsm + B_HI + off) = *(const uint4*)(g_wofh + wo);
            *(uint4*)(dsm + B_LO + off) = *(const uint4*)(g_wofl + wo);
        }
        __syncthreads();

#pragma unroll
        for (int ks = 0; ks < 2; ++ks) {
            uint32_t ah[2][4], al[2][4];
            int arow = m0 + (lane & 15);
            int akcol = ks * 16 + (lane >> 4) * 8;
#pragma unroll
            for (int mt = 0; mt < 2; ++mt) {
                uint32_t aaddr = sbase + A_HI + (uint32_t)(((arow + mt * 16) * ST + akcol) * 2);
                LDSM4(ah[mt], aaddr);
                LDSM4(al[mt], aaddr + (A_LO - A_HI));
            }
            int brow = n0 + (lane & 7);
            int bk = ks * 16 + ((lane >> 3) & 1) * 8;
#pragma unroll
            for (int nt = 0; nt < 12; ++nt) {
                uint32_t baddr = sbase + B_HI + (uint32_t)(((brow + nt * 8) * ST + bk) * 2);
                uint32_t bh[2], bl[2];
                LDSM2(bh, baddr);
                LDSM2(bl, baddr + (B_LO - B_HI));
#pragma unroll
                for (int mt = 0; mt < 2; ++mt) {
                    MMA_BF16(acc[mt][nt], ah[mt], bh);
                    MMA_BF16(acc[mt][nt], ah[mt], bl);
                    MMA_BF16(acc[mt][nt], al[mt], bh);
                }
            }
        }
    }
    __syncthreads();

    // epilogue: per-warp transpose, +bias, write g_off (oc < OCT only)
    float* eps = (float*)(dsm) + w * 8 * 36;
    int pbase = p0 + m0;
    int rq = lane >> 2, cq = (lane & 3) * 2;
#pragma unroll 1
    for (int nt = 0; nt < 12; ++nt) {
#pragma unroll
        for (int mt = 0; mt < 2; ++mt) {
            eps[(cq + 0) * 36 + mt * 16 + rq]     = acc[mt][nt][0];
            eps[(cq + 1) * 36 + mt * 16 + rq]     = acc[mt][nt][1];
            eps[(cq + 0) * 36 + mt * 16 + rq + 8] = acc[mt][nt][2];
            eps[(cq + 1) * 36 + mt * 16 + rq + 8] = acc[mt][nt][3];
        }
        __syncwarp();
#pragma unroll
        for (int oi = 0; oi < 8; ++oi) {
            int oc = n0 + nt * 8 + oi;
            if (oc < OCT) {
                float v = eps[oi * 36 + lane] + g_bo[oc];
                g_off[((size_t)b * OCT + oc) * HW + pbase + lane] = v;
            }
        }
        __syncwarp();
    }
}

// ---------------- K2: deformable depthwise + BN + ReLU ------------------------
#define PLSTRIDE 4164   // 4096 plane + 68 zero pad
template<int K2T, int KT, int SB, int SIDX>
__global__ __launch_bounds__(512) void deform_kernel(
    const float* __restrict__ x, const float* __restrict__ wdw,
    const float* __restrict__ gg, const float* __restrict__ bb,
    const float* __restrict__ mm, const float* __restrict__ vv) {
    extern __shared__ float sm[];
    float* planes = sm;                 // 6 * PLSTRIDE
    float* wdw_s  = sm + 6 * PLSTRIDE;  // 6 * 49
    int tid = threadIdx.x;
    int b = blockIdx.z;
    int p = blockIdx.x * 512 + tid;
    float yf = (float)(p >> 6), xf = (float)(p & 63);
    const float* offb = g_off + ((size_t)b * OCT + SB) * HW + p;
    const float* xb = x + (size_t)b * C_ * HW;

    for (int i = tid; i < 6 * 68; i += 512) {
        int ci = i / 68;
        planes[ci * PLSTRIDE + 4096 + (i % 68)] = 0.f;
    }

    for (int it = 0; it < 2; ++it) {
        int cbase = blockIdx.y * 12 + it * 6;
        __syncthreads();
        for (int i = tid; i < 6 * 1024; i += 512) {
            int ci = i >> 10, j = i & 1023;
            float4 v = *(const float4*)(xb + (size_t)(cbase + ci) * HW + j * 4);
            *(float4*)(planes + ci * PLSTRIDE + j * 4) = v;
        }
        for (int i = tid; i < 6 * K2T; i += 512) {
            int ci = i / K2T, t = i % K2T;
            wdw_s[ci * 49 + t] = wdw[(cbase + ci) * K2T + t];
        }
        __syncthreads();

        float acc[6];
#pragma unroll
        for (int ci = 0; ci < 6; ci++) acc[ci] = 0.f;

        int t = 0;
#pragma unroll 1
        for (int ty = 0; ty < KT; ++ty) {
            float pny = (float)(ty - (KT - 1) / 2);
#pragma unroll
            for (int tx = 0; tx < KT; ++tx, ++t) {
                float pnx = (float)(tx - (KT - 1) / 2);
                float dy = __ldg(offb + (size_t)t * HW);
                float dx = __ldg(offb + (size_t)(K2T + t) * HW);
                float py = fminf(fmaxf(yf + pny + dy, 0.f), 63.f);
                float px = fminf(fmaxf(xf + pnx + dx, 0.f), 63.f);
                float fy = floorf(py), fx = floorf(px);
                float wy = py - fy, wx = px - fx;
                int idx = (int)fy * 64 + (int)fx;
                float w1y = 1.f - wy, w1x = 1.f - wx;
                float w00 = w1y * w1x, w01 = w1y * wx;
                float w10 = wy * w1x,  w11 = wy * wx;
#pragma unroll
                for (int ci = 0; ci < 6; ci++) {
                    const float* pl = planes + ci * PLSTRIDE + idx;
                    float v = w00 * pl[0] + w01 * pl[1] + w10 * pl[64] + w11 * pl[65];
                    acc[ci] = fmaf(wdw_s[ci * 49 + t], v, acc[ci]);
                }
            }
        }
        float vals[6];
#pragma unroll
        for (int ci = 0; ci < 6; ci++) {
            int c = cbase + ci;
            float inv = __ldg(gg + c) * rsqrtf(__ldg(vv + c) + EPSV);
            float sh  = __ldg(bb + c) - __ldg(mm + c) * inv;
            vals[ci] = fmaxf(fmaf(acc[ci], inv, sh), 0.f);
        }
        float* row = g_xc + ((size_t)b * HW + p) * KP + SIDX * 96 + cbase;
        *(float2*)(row + 0) = make_float2(vals[0], vals[1]);
        *(float2*)(row + 2) = make_float2(vals[2], vals[3]);
        *(float2*)(row + 4) = make_float2(vals[4], vals[5]);
    }
}

// ---------------- K3: pointwise GEMM via mma.sync bf16 2-split + BN + ReLU ----
__global__ __launch_bounds__(256) void pw_mma_kernel(
    const float* __restrict__ gp, const float* __restrict__ bp,
    const float* __restrict__ mp, const float* __restrict__ vp,
    float* __restrict__ out) {
    extern __shared__ char dsm[];
    uint32_t sbase = smem_u32(dsm);
    int tid = threadIdx.x, w = tid >> 5, lane = tid & 31;
    int m0 = (w & 3) * 32, n0 = (w >> 2) * 96;
    int P0 = blockIdx.x * 128;
    const float* xrow = g_xc + (size_t)P0 * KP;

    float acc[2][12][4];
#pragma unroll
    for (int i = 0; i < 2; i++)
#pragma unroll
        for (int j = 0; j < 12; j++)
#pragma unroll
            for (int q = 0; q < 4; q++) acc[i][j][q] = 0.f;

    for (int kc = 0; kc < 9; ++kc) {
        __syncthreads();
        for (int i = tid; i < 1024; i += 256) {
            int px = i >> 3, k4 = (i & 7) * 4;
            float4 v = *(const float4*)(xrow + (size_t)px * KP + kc * 32 + k4);
            __nv_bfloat16 h0 = __float2bfloat16(v.x), h1 = __float2bfloat16(v.y);
            __nv_bfloat16 h2 = __float2bfloat16(v.z), h3 = __float2bfloat16(v.w);
            __nv_bfloat16 l0 = __float2bfloat16(v.x - __bfloat162float(h0));
            __nv_bfloat16 l1 = __float2bfloat16(v.y - __bfloat162float(h1));
            __nv_bfloat16 l2 = __float2bfloat16(v.z - __bfloat162float(h2));
            __nv_bfloat16 l3 = __float2bfloat16(v.w - __bfloat162float(h3));
            uint2 hv, lv;
            hv.x = ((uint32_t)__bfloat16_as_ushort(h1) << 16) | __bfloat16_as_ushort(h0);
            hv.y = ((uint32_t)__bfloat16_as_ushort(h3) << 16) | __bfloat16_as_ushort(h2);
            lv.x = ((uint32_t)__bfloat16_as_ushort(l1) << 16) | __bfloat16_as_ushort(l0);
            lv.y = ((uint32_t)__bfloat16_as_ushort(l3) << 16) | __bfloat16_as_ushort(l2);
            int off = (px * ST + k4) * 2;
            *(uint2*)(dsm + A_HI + off) = hv;
            *(uint2*)(dsm + A_LO + off) = lv;
        }
        for (int i = tid; i < 3072; i += 256) {
            int buf = i >= 1536;
            int r = i - buf * 1536;
            int n = r >> 3, k4 = (r & 7) * 4;
            uint2 v = *(const uint2*)((buf ? g_pwl : g_pwh) + n * KP + kc * 32 + k4);
            *(uint2*)(dsm + (buf ? B_LO : B_HI) + (n * ST + k4) * 2) = v;
        }
        __syncthreads();

#pragma unroll
        for (int ks = 0; ks < 2; ++ks) {
            uint32_t ah[2][4], al[2][4];
            int arow = m0 + (lane & 15);
            int akcol = ks * 16 + (lane >> 4) * 8;
#pragma unroll
            for (int mt = 0; mt < 2; ++mt) {
                uint32_t aaddr = sbase + A_HI + (uint32_t)(((arow + mt * 16) * ST + akcol) * 2);
                LDSM4(ah[mt], aaddr);
                LDSM4(al[mt], aaddr + (A_LO - A_HI));
            }
            int brow = n0 + (lane & 7);
            int bk = ks * 16 + ((lane >> 3) & 1) * 8;
#pragma unroll
            for (int nt = 0; nt < 12; ++nt) {
                uint32_t baddr = sbase + B_HI + (uint32_t)(((brow + nt * 8) * ST + bk) * 2);
                uint32_t bh[2], bl[2];
                LDSM2(bh, baddr);
                LDSM2(bl, baddr + (B_LO - B_HI));
#pragma unroll
                for (int mt = 0; mt < 2; ++mt) {
                    MMA_BF16(acc[mt][nt], ah[mt], bh);
                    MMA_BF16(acc[mt][nt], ah[mt], bl);
                    MMA_BF16(acc[mt][nt], al[mt], bh);
                }
            }
        }
    }
    __syncthreads();

    float* eps = (float*)(dsm) + w * 8 * 36;
    int b = P0 >> 12;
    int pbase = (P0 & 4095) + m0;
    int rq = lane >> 2, cq = (lane & 3) * 2;
#pragma unroll 1
    for (int nt = 0; nt < 12; ++nt) {
#pragma unroll
        for (int mt = 0; mt < 2; ++mt) {
            eps[(cq + 0) * 36 + mt * 16 + rq]     = acc[mt][nt][0];
            eps[(cq + 1) * 36 + mt * 16 + rq]     = acc[mt][nt][1];
            eps[(cq + 0) * 36 + mt * 16 + rq + 8] = acc[mt][nt][2];
            eps[(cq + 1) * 36 + mt * 16 + rq + 8] = acc[mt][nt][3];
        }
        __syncwarp();
#pragma unroll
        for (int oi = 0; oi < 8; ++oi) {
            int oc = n0 + nt * 8 + oi;
            float inv = __ldg(gp + oc) * rsqrtf(__ldg(vp + oc) + EPSV);
            float sh  = __ldg(bp + oc) - __ldg(mp + oc) * inv;
            float v = eps[oi * 36 + lane];
            out[((size_t)b * O_ + oc) * HW + pbase + lane] = fmaxf(fmaf(v, inv, sh), 0.f);
        }
        __syncwarp();
    }
}

// ---------------- launch ------------------------------------------------------
extern "C" void kernel_launch(void* const* d_in, const int* in_sizes, int n_in,
                              void* d_out, int out_size) {
    const float* x     = (const float*)d_in[0];
    const float* w3    = (const float*)d_in[1];
    const float* b3    = (const float*)d_in[2];
    const float* wdw3  = (const float*)d_in[3];
    const float* g3    = (const float*)d_in[4];
    const float* be3   = (const float*)d_in[5];
    const float* m3    = (const float*)d_in[6];
    const float* v3    = (const float*)d_in[7];
    const float* w5    = (const float*)d_in[8];
    const float* b5    = (const float*)d_in[9];
    const float* wdw5  = (const float*)d_in[10];
    const float* g5    = (const float*)d_in[11];
    const float* be5   = (const float*)d_in[12];
    const float* m5    = (const float*)d_in[13];
    const float* v5    = (const float*)d_in[14];
    const float* w7    = (const float*)d_in[15];
    const float* b7    = (const float*)d_in[16];
    const float* wdw7  = (const float*)d_in[17];
    const float* g7    = (const float*)d_in[18];
    const float* be7   = (const float*)d_in[19];
    const float* m7    = (const float*)d_in[20];
    const float* v7    = (const float*)d_in[21];
    const float* wpw   = (const float*)d_in[22];
    const float* gp    = (const float*)d_in[23];
    const float* bp    = (const float*)d_in[24];
    const float* mp    = (const float*)d_in[25];
    const float* vp    = (const float*)d_in[26];
    float* out = (float*)d_out;

    int smem_deform = (6 * PLSTRIDE + 6 * 49) * sizeof(float);
    cudaFuncSetAttribute(deform_kernel<9, 3, 0, 0>,
                         cudaFuncAttributeMaxDynamicSharedMemorySize, smem_deform);
    cudaFuncSetAttribute(deform_kernel<25, 5, 18, 1>,
                         cudaFuncAttributeMaxDynamicSharedMemorySize, smem_deform);
    cudaFuncSetAttribute(deform_kernel<49, 7, 68, 2>,
                         cudaFuncAttributeMaxDynamicSharedMemorySize, smem_deform);
    cudaFuncSetAttribute(pw_mma_kernel,
                         cudaFuncAttributeMaxDynamicSharedMemorySize, GEMM_SMEM);
    cudaFuncSetAttribute(offconv_mma_kernel,
                         cudaFuncAttributeMaxDynamicSharedMemorySize, GEMM_SMEM);

    prep_kernel<<<256, 256>>>(w3, b3, w5, b5, w7, b7, wpw);
    xpose_kernel<<<64, 256>>>(x);
    offconv_mma_kernel<<<dim3(32, 1, B_), 256, GEMM_SMEM>>>();
    deform_kernel<9, 3, 0, 0><<<dim3(8, 8, B_), 512, smem_deform>>>(x, wdw3, g3, be3, m3, v3);
    deform_kernel<25, 5, 18, 1><<<dim3(8, 8, B_), 512, smem_deform>>>(x, wdw5, g5, be5, m5, v5);
    deform_kernel<49, 7, 68, 2><<<dim3(8, 8, B_), 512, smem_deform>>>(x, wdw7, g7, be7, m7, v7);
    pw_mma_kernel<<<128, 256, GEMM_SMEM>>>(gp, bp, mp, vp, out);
}

// round 9
// speedup vs baseline: 1.1208x; 1.1208x over previous
#include <cuda_runtime.h>
#include <cuda_bf16.h>
#include <cstdint>

#define EPSV 1e-5f
#define B_   4
#define C_   96
#define HW   4096
#define OCT  166     // 18 + 50 + 98 offset channels
#define OCP  192     // weight-pack padding
#define NOF  168     // offconv GEMM N (166 -> 168)
#define KOF  864     // 9*96 offset-conv K
#define KP   320     // g_xc row stride (288 used)
#define O_   192

// ---------------- scratch (static device globals) -----------------------------
__device__ float g_off[B_ * OCT * HW];          // offset conv output  [b][oc][p]
__device__ float g_xc [B_ * HW * KP];           // deform output, PIXEL-major [b*HW+p][KP]
__device__ float g_bo [OCP];                    // packed offset bias
__device__ __nv_bfloat16 g_xth[B_ * HW * 96];   // x transposed hi [b*HW+p][c]
__device__ __nv_bfloat16 g_xtl[B_ * HW * 96];   // x transposed lo
__device__ __nv_bfloat16 g_wofh[OCP * KOF];     // offset weights hi [oc][tap*96+c]
__device__ __nv_bfloat16 g_wofl[OCP * KOF];     // offset weights lo
__device__ __nv_bfloat16 g_pwh[O_ * KP];        // pointwise weights hi [o][KP]
__device__ __nv_bfloat16 g_pwl[O_ * KP];        // pointwise weights lo [o][KP]

__device__ __forceinline__ uint32_t smem_u32(const void* p) {
    uint32_t a;
    asm("{ .reg .u64 t; cvta.to.shared.u64 t, %1; cvt.u32.u64 %0, t; }" : "=r"(a) : "l"(p));
    return a;
}
#define LDSM4(r, addr) \
    asm volatile("ldmatrix.sync.aligned.m8n8.x4.shared.b16 {%0,%1,%2,%3}, [%4];" \
        : "=r"((r)[0]), "=r"((r)[1]), "=r"((r)[2]), "=r"((r)[3]) : "r"(addr))
#define LDSM2(r, addr) \
    asm volatile("ldmatrix.sync.aligned.m8n8.x2.shared.b16 {%0,%1}, [%2];" \
        : "=r"((r)[0]), "=r"((r)[1]) : "r"(addr))
#define MMA_BF16(d, a, b) \
    asm volatile("mma.sync.aligned.m16n8k16.row.col.f32.bf16.bf16.f32 " \
        "{%0,%1,%2,%3}, {%4,%5,%6,%7}, {%8,%9}, {%0,%1,%2,%3};" \
        : "+f"((d)[0]), "+f"((d)[1]), "+f"((d)[2]), "+f"((d)[3]) \
        : "r"((a)[0]), "r"((a)[1]), "r"((a)[2]), "r"((a)[3]), "r"((b)[0]), "r"((b)[1]))

// ---------------- prep: pack + bf16-split weights -----------------------------
__global__ void prep_kernel(const float* __restrict__ w3, const float* __restrict__ b3,
                            const float* __restrict__ w5, const float* __restrict__ b5,
                            const float* __restrict__ w7, const float* __restrict__ b7,
                            const float* __restrict__ wpw) {
    int i0 = blockIdx.x * blockDim.x + threadIdx.x;
    int stride = gridDim.x * blockDim.x;
    for (int idx = i0; idx < OCP * KOF; idx += stride) {
        int oc = idx / KOF, k = idx % KOF;
        int r = k / 96, c = k % 96;
        float v = 0.f;
        if (oc < 18)        v = w3[(oc * C_ + c) * 9 + r];
        else if (oc < 68)   v = w5[((oc - 18) * C_ + c) * 9 + r];
        else if (oc < OCT)  v = w7[((oc - 68) * C_ + c) * 9 + r];
        __nv_bfloat16 h = __float2bfloat16(v);
        g_wofh[idx] = h;
        g_wofl[idx] = __float2bfloat16(v - __bfloat162float(h));
    }
    for (int idx = i0; idx < OCP; idx += stride) {
        float v = 0.f;
        if (idx < 18)       v = b3[idx];
        else if (idx < 68)  v = b5[idx - 18];
        else if (idx < OCT) v = b7[idx - 68];
        g_bo[idx] = v;
    }
    for (int idx = i0; idx < O_ * KP; idx += stride) {
        int n = idx / KP, k = idx % KP;
        float w = (k < 288) ? wpw[n * 288 + k] : 0.f;
        __nv_bfloat16 h = __float2bfloat16(w);
        g_pwh[idx] = h;
        g_pwl[idx] = __float2bfloat16(w - __bfloat162float(h));
    }
}

// ---------------- xpose: x [b][c][p] -> pixel-major bf16 hi/lo (coalesced) -----
// 256 blocks x 256 threads; each block transposes 64 px x 96 ch via smem.
__global__ __launch_bounds__(256) void xpose_kernel(const float* __restrict__ x) {
    __shared__ float st[64][97];
    int tid = threadIdx.x;
    int g0 = blockIdx.x * 64;              // global pixel index (b*HW+p)
    int b = g0 >> 12, p0 = g0 & 4095;
    const float* src = x + (size_t)b * C_ * HW + p0;
    for (int i = tid; i < 96 * 64; i += 256) {
        int c = i >> 6, px = i & 63;
        st[px][c] = src[(size_t)c * HW + px];
    }
    __syncthreads();
    for (int i = tid; i < 64 * 12; i += 256) {
        int px = i / 12, seg = i - px * 12;
        __nv_bfloat16 h8[8], l8[8];
#pragma unroll
        for (int j = 0; j < 8; ++j) {
            float v = st[px][seg * 8 + j];
            h8[j] = __float2bfloat16(v);
            l8[j] = __float2bfloat16(v - __bfloat162float(h8[j]));
        }
        size_t o = (size_t)(g0 + px) * 96 + seg * 8;
        *(uint4*)(g_xth + o) = *(uint4*)h8;
        *(uint4*)(g_xtl + o) = *(uint4*)l8;
    }
}

// ---------------- K1: offset conv as HMMA implicit GEMM ------------------------
// grid (32 pixel-tiles of 128 px, 1, 4 batch), 256 threads = 8 warps (4M x 2N).
// M=128 px, N=168 oc (group0: 96, group1: 72), K per chunk = one tap (96 ch).
#define OST   104                          // bf16 per smem row (208 B stride)
#define OA_HI 0
#define OA_LO 26624
#define OB_HI 53248
#define OB_LO 88192
#define OFF_SMEM 123136

__global__ __launch_bounds__(256) void offconv_mma_kernel() {
    extern __shared__ char dsm[];
    uint32_t sbase = smem_u32(dsm);
    int tid = threadIdx.x, w = tid >> 5, lane = tid & 31;
    int m0 = (w & 3) * 32;
    int ng = w >> 2, n0 = ng * 96;
    int NT = ng ? 9 : 12;
    int b = blockIdx.z;
    int r0 = blockIdx.x * 2;
    int p0 = blockIdx.x * 128;

    float acc[2][12][4];
#pragma unroll
    for (int i = 0; i < 2; i++)
#pragma unroll
        for (int j = 0; j < 12; j++)
#pragma unroll
            for (int q = 0; q < 4; q++) acc[i][j][q] = 0.f;

    for (int tap = 0; tap < 9; ++tap) {
        int ky = tap / 3 - 1, kx = tap % 3 - 1;
        __syncthreads();
        // stage A: 128 shifted pixels x 96 ch, hi+lo (3072 segs of 16B)
        for (int i = tid; i < 3072; i += 256) {
            int buf = i >= 1536;
            int r = i - buf * 1536;
            int px = r / 12, seg = r - px * 12;
            int row = (px >> 6) + r0 + ky;
            int col = (px & 63) + kx;
            uint32_t off = (uint32_t)(px * OST + seg * 8) * 2 + (buf ? OA_LO : OA_HI);
            if ((unsigned)row < 64u && (unsigned)col < 64u) {
                size_t bp = ((size_t)b * HW + row * 64 + col) * 96 + seg * 8;
                *(uint4*)(dsm + off) = *(const uint4*)((buf ? g_xtl : g_xth) + bp);
            } else {
                uint4 z = {0u, 0u, 0u, 0u};
                *(uint4*)(dsm + off) = z;
            }
        }
        // stage B: 168 oc x 96 ch, hi+lo (4032 segs of 16B)
        for (int i = tid; i < 4032; i += 256) {
            int buf = i >= 2016;
            int r = i - buf * 2016;
            int n = r / 12, seg = r - n * 12;
            size_t wo = (size_t)n * KOF + tap * 96 + seg * 8;
            uint32_t off = (uint32_t)(n * OST + seg * 8) * 2 + (buf ? OB_LO : OB_HI);
            *(uint4*)(dsm + off) = *(const uint4*)((buf ? g_wofl : g_wofh) + wo);
        }
        __syncthreads();

#pragma unroll
        for (int ks = 0; ks < 6; ++ks) {
            uint32_t ah[2][4], al[2][4];
            int arow = m0 + (lane & 15);
            int akcol = ks * 16 + (lane >> 4) * 8;
#pragma unroll
            for (int mt = 0; mt < 2; ++mt) {
                uint32_t aaddr = sbase + OA_HI + (uint32_t)(((arow + mt * 16) * OST + akcol) * 2);
                LDSM4(ah[mt], aaddr);
                LDSM4(al[mt], aaddr + (OA_LO - OA_HI));
            }
            int brow = n0 + (lane & 7);
            int bk = ks * 16 + ((lane >> 3) & 1) * 8;
#pragma unroll 1
            for (int nt = 0; nt < NT; ++nt) {
                uint32_t baddr = sbase + OB_HI + (uint32_t)(((brow + nt * 8) * OST + bk) * 2);
                uint32_t bh[2], bl[2];
                LDSM2(bh, baddr);
                LDSM2(bl, baddr + (OB_LO - OB_HI));
#pragma unroll
                for (int mt = 0; mt < 2; ++mt) {
                    MMA_BF16(acc[mt][nt], ah[mt], bh);
                    MMA_BF16(acc[mt][nt], ah[mt], bl);
                    MMA_BF16(acc[mt][nt], al[mt], bh);
                }
            }
        }
    }
    __syncthreads();

    // epilogue: per-warp transpose, +bias, write g_off (oc < OCT only)
    float* eps = (float*)(dsm) + w * 8 * 36;
    int pbase = p0 + m0;
    int rq = lane >> 2, cq = (lane & 3) * 2;
#pragma unroll 1
    for (int nt = 0; nt < NT; ++nt) {
#pragma unroll
        for (int mt = 0; mt < 2; ++mt) {
            eps[(cq + 0) * 36 + mt * 16 + rq]     = acc[mt][nt][0];
            eps[(cq + 1) * 36 + mt * 16 + rq]     = acc[mt][nt][1];
            eps[(cq + 0) * 36 + mt * 16 + rq + 8] = acc[mt][nt][2];
            eps[(cq + 1) * 36 + mt * 16 + rq + 8] = acc[mt][nt][3];
        }
        __syncwarp();
#pragma unroll
        for (int oi = 0; oi < 8; ++oi) {
            int oc = n0 + nt * 8 + oi;
            if (oc < OCT) {
                float v = eps[oi * 36 + lane] + g_bo[oc];
                g_off[((size_t)b * OCT + oc) * HW + pbase + lane] = v;
            }
        }
        __syncwarp();
    }
}

// ---------------- K2: deformable depthwise + BN + ReLU ------------------------
#define PLSTRIDE 4164   // 4096 plane + 68 zero pad
template<int K2T, int KT, int SB, int SIDX>
__global__ __launch_bounds__(512) void deform_kernel(
    const float* __restrict__ x, const float* __restrict__ wdw,
    const float* __restrict__ gg, const float* __restrict__ bb,
    const float* __restrict__ mm, const float* __restrict__ vv) {
    extern __shared__ float sm[];
    float* planes = sm;                 // 6 * PLSTRIDE
    float* wdw_s  = sm + 6 * PLSTRIDE;  // 6 * 49
    int tid = threadIdx.x;
    int b = blockIdx.z;
    int p = blockIdx.x * 512 + tid;
    float yf = (float)(p >> 6), xf = (float)(p & 63);
    const float* offb = g_off + ((size_t)b * OCT + SB) * HW + p;
    const float* xb = x + (size_t)b * C_ * HW;

    for (int i = tid; i < 6 * 68; i += 512) {
        int ci = i / 68;
        planes[ci * PLSTRIDE + 4096 + (i % 68)] = 0.f;
    }

    for (int it = 0; it < 2; ++it) {
        int cbase = blockIdx.y * 12 + it * 6;
        __syncthreads();
        for (int i = tid; i < 6 * 1024; i += 512) {
            int ci = i >> 10, j = i & 1023;
            float4 v = *(const float4*)(xb + (size_t)(cbase + ci) * HW + j * 4);
            *(float4*)(planes + ci * PLSTRIDE + j * 4) = v;
        }
        for (int i = tid; i < 6 * K2T; i += 512) {
            int ci = i / K2T, t = i % K2T;
            wdw_s[ci * 49 + t] = wdw[(cbase + ci) * K2T + t];
        }
        __syncthreads();

        float acc[6];
#pragma unroll
        for (int ci = 0; ci < 6; ci++) acc[ci] = 0.f;

        int t = 0;
#pragma unroll 1
        for (int ty = 0; ty < KT; ++ty) {
            float pny = (float)(ty - (KT - 1) / 2);
#pragma unroll
            for (int tx = 0; tx < KT; ++tx, ++t) {
                float pnx = (float)(tx - (KT - 1) / 2);
                float dy = __ldg(offb + (size_t)t * HW);
                float dx = __ldg(offb + (size_t)(K2T + t) * HW);
                float py = fminf(fmaxf(yf + pny + dy, 0.f), 63.f);
                float px = fminf(fmaxf(xf + pnx + dx, 0.f), 63.f);
                float fy = floorf(py), fx = floorf(px);
                float wy = py - fy, wx = px - fx;
                int idx = (int)fy * 64 + (int)fx;
                float w1y = 1.f - wy, w1x = 1.f - wx;
                float w00 = w1y * w1x, w01 = w1y * wx;
                float w10 = wy * w1x,  w11 = wy * wx;
#pragma unroll
                for (int ci = 0; ci < 6; ci++) {
                    const float* pl = planes + ci * PLSTRIDE + idx;
                    float v = w00 * pl[0] + w01 * pl[1] + w10 * pl[64] + w11 * pl[65];
                    acc[ci] = fmaf(wdw_s[ci * 49 + t], v, acc[ci]);
                }
            }
        }
        float vals[6];
#pragma unroll
        for (int ci = 0; ci < 6; ci++) {
            int c = cbase + ci;
            float inv = __ldg(gg + c) * rsqrtf(__ldg(vv + c) + EPSV);
            float sh  = __ldg(bb + c) - __ldg(mm + c) * inv;
            vals[ci] = fmaxf(fmaf(acc[ci], inv, sh), 0.f);
        }
        float* row = g_xc + ((size_t)b * HW + p) * KP + SIDX * 96 + cbase;
        *(float2*)(row + 0) = make_float2(vals[0], vals[1]);
        *(float2*)(row + 2) = make_float2(vals[2], vals[3]);
        *(float2*)(row + 4) = make_float2(vals[4], vals[5]);
    }
}

// ---------------- K3: pointwise GEMM via mma.sync bf16 2-split + BN + ReLU ----
#define ST    56
#define A_HI  0
#define A_LO  14336
#define B_HI  28672
#define B_LO  50176
#define PW_SMEM 71680

__global__ __launch_bounds__(256) void pw_mma_kernel(
    const float* __restrict__ gp, const float* __restrict__ bp,
    const float* __restrict__ mp, const float* __restrict__ vp,
    float* __restrict__ out) {
    extern __shared__ char dsm[];
    uint32_t sbase = smem_u32(dsm);
    int tid = threadIdx.x, w = tid >> 5, lane = tid & 31;
    int m0 = (w & 3) * 32, n0 = (w >> 2) * 96;
    int P0 = blockIdx.x * 128;
    const float* xrow = g_xc + (size_t)P0 * KP;

    float acc[2][12][4];
#pragma unroll
    for (int i = 0; i < 2; i++)
#pragma unroll
        for (int j = 0; j < 12; j++)
#pragma unroll
            for (int q = 0; q < 4; q++) acc[i][j][q] = 0.f;

    for (int kc = 0; kc < 9; ++kc) {
        __syncthreads();
        for (int i = tid; i < 1024; i += 256) {
            int px = i >> 3, k4 = (i & 7) * 4;
            float4 v = *(const float4*)(xrow + (size_t)px * KP + kc * 32 + k4);
            __nv_bfloat16 h0 = __float2bfloat16(v.x), h1 = __float2bfloat16(v.y);
            __nv_bfloat16 h2 = __float2bfloat16(v.z), h3 = __float2bfloat16(v.w);
            __nv_bfloat16 l0 = __float2bfloat16(v.x - __bfloat162float(h0));
            __nv_bfloat16 l1 = __float2bfloat16(v.y - __bfloat162float(h1));
            __nv_bfloat16 l2 = __float2bfloat16(v.z - __bfloat162float(h2));
            __nv_bfloat16 l3 = __float2bfloat16(v.w - __bfloat162float(h3));
            uint2 hv, lv;
            hv.x = ((uint32_t)__bfloat16_as_ushort(h1) << 16) | __bfloat16_as_ushort(h0);
            hv.y = ((uint32_t)__bfloat16_as_ushort(h3) << 16) | __bfloat16_as_ushort(h2);
            lv.x = ((uint32_t)__bfloat16_as_ushort(l1) << 16) | __bfloat16_as_ushort(l0);
            lv.y = ((uint32_t)__bfloat16_as_ushort(l3) << 16) | __bfloat16_as_ushort(l2);
            int off = (px * ST + k4) * 2;
            *(uint2*)(dsm + A_HI + off) = hv;
            *(uint2*)(dsm + A_LO + off) = lv;
        }
        for (int i = tid; i < 3072; i += 256) {
            int buf = i >= 1536;
            int r = i - buf * 1536;
            int n = r >> 3, k4 = (r & 7) * 4;
            uint2 v = *(const uint2*)((buf ? g_pwl : g_pwh) + n * KP + kc * 32 + k4);
            *(uint2*)(dsm + (buf ? B_LO : B_HI) + (n * ST + k4) * 2) = v;
        }
        __syncthreads();

#pragma unroll
        for (int ks = 0; ks < 2; ++ks) {
            uint32_t ah[2][4], al[2][4];
            int arow = m0 + (lane & 15);
            int akcol = ks * 16 + (lane >> 4) * 8;
#pragma unroll
            for (int mt = 0; mt < 2; ++mt) {
                uint32_t aaddr = sbase + A_HI + (uint32_t)(((arow + mt * 16) * ST + akcol) * 2);
                LDSM4(ah[mt], aaddr);
                LDSM4(al[mt], aaddr + (A_LO - A_HI));
            }
            int brow = n0 + (lane & 7);
            int bk = ks * 16 + ((lane >> 3) & 1) * 8;
#pragma unroll
            for (int nt = 0; nt < 12; ++nt) {
                uint32_t baddr = sbase + B_HI + (uint32_t)(((brow + nt * 8) * ST + bk) * 2);
                uint32_t bh[2], bl[2];
                LDSM2(bh, baddr);
                LDSM2(bl, baddr + (B_LO - B_HI));
#pragma unroll
                for (int mt = 0; mt < 2; ++mt) {
                    MMA_BF16(acc[mt][nt], ah[mt], bh);
                    MMA_BF16(acc[mt][nt], ah[mt], bl);
                    MMA_BF16(acc[mt][nt], al[mt], bh);
                }
            }
        }
    }
    __syncthreads();

    float* eps = (float*)(dsm) + w * 8 * 36;
    int b = P0 >> 12;
    int pbase = (P0 & 4095) + m0;
    int rq = lane >> 2, cq = (lane & 3) * 2;
#pragma unroll 1
    for (int nt = 0; nt < 12; ++nt) {
#pragma unroll
        for (int mt = 0; mt < 2; ++mt) {
            eps[(cq + 0) * 36 + mt * 16 + rq]     = acc[mt][nt][0];
            eps[(cq + 1) * 36 + mt * 16 + rq]     = acc[mt][nt][1];
            eps[(cq + 0) * 36 + mt * 16 + rq + 8] = acc[mt][nt][2];
            eps[(cq + 1) * 36 + mt * 16 + rq + 8] = acc[mt][nt][3];
        }
        __syncwarp();
#pragma unroll
        for (int oi = 0; oi < 8; ++oi) {
            int oc = n0 + nt * 8 + oi;
            float inv = __ldg(gp + oc) * rsqrtf(__ldg(vp + oc) + EPSV);
            float sh  = __ldg(bp + oc) - __ldg(mp + oc) * inv;
            float v = eps[oi * 36 + lane];
            out[((size_t)b * O_ + oc) * HW + pbase + lane] = fmaxf(fmaf(v, inv, sh), 0.f);
        }
        __syncwarp();
    }
}

// ---------------- launch ------------------------------------------------------
extern "C" void kernel_launch(void* const* d_in, const int* in_sizes, int n_in,
                              void* d_out, int out_size) {
    const float* x     = (const float*)d_in[0];
    const float* w3    = (const float*)d_in[1];
    const float* b3    = (const float*)d_in[2];
    const float* wdw3  = (const float*)d_in[3];
    const float* g3    = (const float*)d_in[4];
    const float* be3   = (const float*)d_in[5];
    const float* m3    = (const float*)d_in[6];
    const float* v3    = (const float*)d_in[7];
    const float* w5    = (const float*)d_in[8];
    const float* b5    = (const float*)d_in[9];
    const float* wdw5  = (const float*)d_in[10];
    const float* g5    = (const float*)d_in[11];
    const float* be5   = (const float*)d_in[12];
    const float* m5    = (const float*)d_in[13];
    const float* v5    = (const float*)d_in[14];
    const float* w7    = (const float*)d_in[15];
    const float* b7    = (const float*)d_in[16];
    const float* wdw7  = (const float*)d_in[17];
    const float* g7    = (const float*)d_in[18];
    const float* be7   = (const float*)d_in[19];
    const float* m7    = (const float*)d_in[20];
    const float* v7    = (const float*)d_in[21];
    const float* wpw   = (const float*)d_in[22];
    const float* gp    = (const float*)d_in[23];
    const float* bp    = (const float*)d_in[24];
    const float* mp    = (const float*)d_in[25];
    const float* vp    = (const float*)d_in[26];
    float* out = (float*)d_out;

    int smem_deform = (6 * PLSTRIDE + 6 * 49) * sizeof(float);
    cudaFuncSetAttribute(deform_kernel<9, 3, 0, 0>,
                         cudaFuncAttributeMaxDynamicSharedMemorySize, smem_deform);
    cudaFuncSetAttribute(deform_kernel<25, 5, 18, 1>,
                         cudaFuncAttributeMaxDynamicSharedMemorySize, smem_deform);
    cudaFuncSetAttribute(deform_kernel<49, 7, 68, 2>,
                         cudaFuncAttributeMaxDynamicSharedMemorySize, smem_deform);
    cudaFuncSetAttribute(pw_mma_kernel,
                         cudaFuncAttributeMaxDynamicSharedMemorySize, PW_SMEM);
    cudaFuncSetAttribute(offconv_mma_kernel,
                         cudaFuncAttributeMaxDynamicSharedMemorySize, OFF_SMEM);

    prep_kernel<<<256, 256>>>(w3, b3, w5, b5, w7, b7, wpw);
    xpose_kernel<<<256, 256>>>(x);
    offconv_mma_kernel<<<dim3(32, 1, B_), 256, OFF_SMEM>>>();
    deform_kernel<9, 3, 0, 0><<<dim3(8, 8, B_), 512, smem_deform>>>(x, wdw3, g3, be3, m3, v3);
    deform_kernel<25, 5, 18, 1><<<dim3(8, 8, B_), 512, smem_deform>>>(x, wdw5, g5, be5, m5, v5);
    deform_kernel<49, 7, 68, 2><<<dim3(8, 8, B_), 512, smem_deform>>>(x, wdw7, g7, be7, m7, v7);
    pw_mma_kernel<<<128, 256, PW_SMEM>>>(gp, bp, mp, vp, out);
}